// round 1
// baseline (speedup 1.0000x reference)
#include <cuda_runtime.h>

// PreampGainLayer: DK-method preamp, FFT-domain circular filtering.
// Inputs (metadata order): x[B*2048], cond[B], state[B*4096],
//   alpha_rg[1], alpha_r1[1], alpha_c1[1], alpha_c2[1], cond_w[1], cond_b[1]
// Output: float[B*2048]

#define MM 2048   // complex FFT size (real length 4096)
#define PI_D 3.14159265358979323846

// twiddle table: {sin(pi*k/2048), 1 - cos(pi*k/2048)} computed in fp64
__device__ float2 g_tw[2049];
// per-batch filter params: DC, DS, DI, NC, NS, NI (6 used, stride 8)
__device__ float g_params[2048 * 8];

// ---------------------------------------------------------------------------
// init kernels
// ---------------------------------------------------------------------------
__global__ void init_tw_kernel() {
    int k = blockIdx.x * blockDim.x + threadIdx.x;
    if (k <= 2048) {
        double th = PI_D * (double)k / 2048.0;
        double s, c;
        sincos(th, &s, &c);
        g_tw[k] = make_float2((float)s, (float)(1.0 - c));
    }
}

__device__ void inv4(const double A[4][4], double O[4][4]) {
    double a[4][8];
    for (int r = 0; r < 4; r++) {
        for (int c = 0; c < 4; c++) a[r][c] = A[r][c];
        for (int c = 0; c < 4; c++) a[r][4 + c] = (r == c) ? 1.0 : 0.0;
    }
    for (int col = 0; col < 4; col++) {
        int piv = col;
        for (int r = col + 1; r < 4; r++)
            if (fabs(a[r][col]) > fabs(a[piv][col])) piv = r;
        if (piv != col)
            for (int c = 0; c < 8; c++) { double t = a[col][c]; a[col][c] = a[piv][c]; a[piv][c] = t; }
        double inv = 1.0 / a[col][col];
        for (int c = 0; c < 8; c++) a[col][c] *= inv;
        for (int r = 0; r < 4; r++) {
            if (r == col) continue;
            double f = a[r][col];
            for (int c = 0; c < 8; c++) a[r][c] -= f * a[col][c];
        }
    }
    for (int r = 0; r < 4; r++)
        for (int c = 0; c < 4; c++) O[r][c] = a[r][4 + c];
}

__global__ void init_params_kernel(const float* __restrict__ cond,
                                   const float* __restrict__ a_rg,
                                   const float* __restrict__ a_r1,
                                   const float* __restrict__ a_c1,
                                   const float* __restrict__ a_c2,
                                   const float* __restrict__ cw,
                                   const float* __restrict__ cb,
                                   int B) {
    int b = blockIdx.x * blockDim.x + threadIdx.x;
    if (b >= B) return;

    const double T = 1.0 / 44100.0;
    auto sig = [](double v) { return 1.0 / (1.0 + exp(-v)); };

    double RG = (0.9 + sig((double)a_rg[0]) * 0.2) * 1.0e6;
    double R1 = (0.99 + sig((double)a_r1[0]) * 0.02) * 4.7e5;
    double C1 = (0.9 + sig((double)a_c1[0]) * 0.2) * 3.3e-9;
    double C2 = (0.9 + sig((double)a_c2[0]) * 0.2) * 1.0e-9;

    double gr  = 1.0 / R1;
    double gx1 = 2.0 * C1 / T;
    double gx2 = 2.0 * C2 / T;

    // S0 = [[Nr'Gr Nr + Nx'Gx Nx, Nu'],[Nu, 0]]
    double S[4][4] = {{gx1, -gx1, 0.0, 1.0},
                      {-gx1, gx1 + gr, 0.0, 0.0},
                      {0.0, 0.0, gx2, 0.0},
                      {1.0, 0.0, 0.0, 0.0}};
    double Si[4][4];
    inv4(S, Si);

    // PV = Si * Nvp^T  (Nvp rows: (0,1,-1,0),(0,0,1,0))
    double PV[4][2], PX[4][2], PU[4];
    for (int i = 0; i < 4; i++) {
        PV[i][0] = Si[i][1] - Si[i][2];
        PV[i][1] = Si[i][2];
        PX[i][0] = Si[i][0] - Si[i][1];  // Nxp rows: (1,-1,0,0),(0,0,1,0)
        PX[i][1] = Si[i][2];
        PU[i]    = Si[i][3];
    }
    double Q[2][2], Ux[2][2];
    for (int c = 0; c < 2; c++) {
        Q[0][c]  = PV[1][c] - PV[2][c];
        Q[1][c]  = PV[2][c];
        Ux[0][c] = PV[0][c] - PV[1][c];
        Ux[1][c] = PV[2][c];
    }
    double UoV[2] = {PV[2][0], PV[2][1]};
    double Uu[2]  = {PV[3][0], PV[3][1]};
    double NXX[2][2];
    for (int c = 0; c < 2; c++) { NXX[0][c] = PX[0][c] - PX[1][c]; NXX[1][c] = PX[2][c]; }
    double zg1 = 2.0 * gx1, zg2 = 2.0 * gx2;
    double Ao[2][2] = {{zg1 * NXX[0][0] - 1.0, zg1 * NXX[0][1]},
                       {zg2 * NXX[1][0], zg2 * NXX[1][1] - 1.0}};
    double BXU0 = PU[0] - PU[1], BXU1 = PU[2];
    double Bo[2] = {zg1 * BXU0, zg2 * BXU1};
    double Do[2] = {PX[2][0], PX[2][1]};
    double Eo = PU[2];

    // conditioning -> pot position
    double pot = sig((double)cond[b] * (double)cw[0] + (double)cb[0]);
    double p = (pow(10.0, pot) - 1.0) / 9.0;
    p = fmin(fmax(p, 1e-4), 1.0 - 1e-4);
    double d0 = (1.0 - p) * RG, d1 = p * RG;

    // K = inv(Rv + Q)
    double M00 = d0 + Q[0][0], M01 = Q[0][1], M10 = Q[1][0], M11 = d1 + Q[1][1];
    double idet = 1.0 / (M00 * M11 - M01 * M10);
    double K[2][2] = {{M11 * idet, -M01 * idet}, {-M10 * idet, M00 * idet}};

    double ZU[2][2] = {{zg1 * Ux[0][0], zg1 * Ux[0][1]},
                       {zg2 * Ux[1][0], zg2 * Ux[1][1]}};
    double t1[2][2];
    for (int r = 0; r < 2; r++)
        for (int c = 0; c < 2; c++)
            t1[r][c] = ZU[r][0] * K[0][c] + ZU[r][1] * K[1][c];

    double A2[2][2], Bm[2], Dm[2];
    for (int r = 0; r < 2; r++)
        for (int c = 0; c < 2; c++)
            A2[r][c] = Ao[r][c] - (t1[r][0] * Ux[c][0] + t1[r][1] * Ux[c][1]);
    for (int r = 0; r < 2; r++)
        Bm[r] = Bo[r] - (t1[r][0] * Uu[0] + t1[r][1] * Uu[1]);
    double UoK[2];
    for (int c = 0; c < 2; c++)
        UoK[c] = UoV[0] * K[0][c] + UoV[1] * K[1][c];
    for (int c = 0; c < 2; c++)
        Dm[c] = Do[c] - (UoK[0] * Ux[c][0] + UoK[1] * Ux[c][1]);
    double Em = Eo - (UoK[0] * Uu[0] + UoK[1] * Uu[1]);

    double tr  = A2[0][0] + A2[1][1];
    double det = A2[0][0] * A2[1][1] - A2[0][1] * A2[1][0];
    double m2[2][2];
    for (int r = 0; r < 2; r++)
        for (int c = 0; c < 2; c++)
            m2[r][c] = A2[r][c] - Bm[r] * Dm[c];
    double tr2  = m2[0][0] + m2[1][1];
    double det2 = m2[0][0] * m2[1][1] - m2[0][1] * m2[1][0];

    double n0 = Em;
    double n1 = -tr2 - (Em - 1.0) * tr;
    double n2 = det2 + (Em - 1.0) * det;

    float* P = &g_params[b * 8];
    P[0] = (float)(1.0 - tr + det);   // DC
    P[1] = (float)(1.0 + det);        // DS
    P[2] = (float)(det - 1.0);        // DI
    P[3] = (float)(n0 + n1 + n2);     // NC
    P[4] = (float)(n0 + n2);          // NS
    P[5] = (float)(n2 - n0);          // NI
}

// ---------------------------------------------------------------------------
// FFT filter kernel: one CTA per batch row
// ---------------------------------------------------------------------------
__device__ __forceinline__ float2 heval(float sn, float omc,
                                        float DC, float DS, float DI,
                                        float NC, float NS, float NI) {
    float nr = NC - NS * omc;
    float ni = NI * sn;
    float dr = DC - DS * omc;
    float di = DI * sn;
    float inv = 1.0f / (dr * dr + di * di);
    return make_float2((nr * dr + ni * di) * inv, (ni * dr - nr * di) * inv);
}

__global__ __launch_bounds__(256) void preamp_fft_kernel(
    const float* __restrict__ x, const float* __restrict__ state,
    float* __restrict__ out) {
    __shared__ float2 sA[MM];
    __shared__ float2 sB[MM];

    const int b = blockIdx.x;
    const int t = threadIdx.x;

    // pack real input (state tail 2048 samples, then x 2048 samples) as complex
    const float2* st2 = (const float2*)state + (size_t)b * 2048 + 1024;
    const float2* x2  = (const float2*)x + (size_t)b * 1024;
    for (int k = t; k < 1024; k += 256) sA[k] = st2[k];
    for (int k = t; k < 1024; k += 256) sA[1024 + k] = x2[k];

    const float* P = &g_params[b * 8];
    const float DC = P[0], DS = P[1], DI = P[2], NC = P[3], NS = P[4], NI = P[5];

    __syncthreads();

    float2* cur = sA;
    float2* nxt = sB;

    // ---- forward FFT (Stockham, DIF, e^{-i}) ----
    for (int m = 1; m <= 1024; m <<= 1) {
#pragma unroll
        for (int it = 0; it < 4; it++) {
            int i  = t + it * 256;
            int q  = i & (m - 1);
            int pm = i - q;                 // p*m
            float2 a  = cur[i];
            float2 bb = cur[i + 1024];
            float2 w  = g_tw[pm << 1];      // angle = pi*p/l
            float wc = 1.0f - w.y;
            float ws = -w.x;
            float dr = a.x - bb.x, di2 = a.y - bb.y;
            int o = (pm << 1) + q;
            nxt[o]     = make_float2(a.x + bb.x, a.y + bb.y);
            nxt[o + m] = make_float2(wc * dr - ws * di2, wc * di2 + ws * dr);
        }
        __syncthreads();
        float2* tmp = cur; cur = nxt; nxt = tmp;
    }
    // cur == U (packed forward FFT)

    // ---- untangle -> rfft bins, multiply by h, repack -> V ----
    for (int k = t; k <= 1024; k += 256) {
        if (k == 0) {
            float2 U0 = cur[0];
            float X0 = U0.x + U0.y;
            float XM = U0.x - U0.y;
            float h0 = NC / DC;
            float hM = (NC - 2.0f * NS) / (DC - 2.0f * DS);
            float Y0 = h0 * X0, YM = hM * XM;
            nxt[0] = make_float2(0.5f * (Y0 + YM), 0.5f * (Y0 - YM));
        } else if (k == 1024) {
            float2 U = cur[1024];
            float2 h = heval(1.0f, 1.0f, DC, DS, DI, NC, NS, NI);
            // Y = h * conj(U); V = conj(Y)
            float yr = h.x * U.x + h.y * U.y;
            float yi = h.y * U.x - h.x * U.y;
            nxt[1024] = make_float2(yr, -yi);
        } else {
            float2 Uk = cur[k];
            float2 Um = cur[2048 - k];
            float2 tw = g_tw[k];
            float sn = tw.x, omc = tw.y;
            float cs = 1.0f - omc;
            float uer = 0.5f * (Uk.x + Um.x), uei = 0.5f * (Uk.y - Um.y);
            float uor = 0.5f * (Uk.y + Um.y), uoi = -0.5f * (Uk.x - Um.x);
            // X[k] = Ue + (cs,-sn)*Uo
            float xr = uer + cs * uor + sn * uoi;
            float xi = uei + cs * uoi - sn * uor;
            // X[M-k] = conj(Ue) - (cs,sn)*conj(Uo)
            float xmr = uer - (cs * uor + sn * uoi);
            float xmi = -uei - (sn * uor - cs * uoi);
            float2 hk = heval(sn, omc, DC, DS, DI, NC, NS, NI);
            float2 hm = heval(sn, 2.0f - omc, DC, DS, DI, NC, NS, NI);
            float ykr = hk.x * xr - hk.y * xi, yki = hk.x * xi + hk.y * xr;
            float ymr = hm.x * xmr - hm.y * xmi, ymi = hm.x * xmi + hm.y * xmr;
            // Ye = (Yk + conj(Ym))/2 ; Yo = W^{+k} * (Yk - conj(Ym))/2
            float yer = 0.5f * (ykr + ymr), yei = 0.5f * (yki - ymi);
            float zr  = 0.5f * (ykr - ymr), zi  = 0.5f * (yki + ymi);
            float yor = cs * zr - sn * zi, yoi = cs * zi + sn * zr;
            nxt[k]        = make_float2(yer - yoi, yei + yor);
            nxt[2048 - k] = make_float2(yer + yoi, yor - yei);
        }
    }
    __syncthreads();
    { float2* tmp = cur; cur = nxt; nxt = tmp; }  // cur == V

    // ---- inverse FFT (e^{+i}) ----
    for (int m = 1; m <= 1024; m <<= 1) {
#pragma unroll
        for (int it = 0; it < 4; it++) {
            int i  = t + it * 256;
            int q  = i & (m - 1);
            int pm = i - q;
            float2 a  = cur[i];
            float2 bb = cur[i + 1024];
            float2 w  = g_tw[pm << 1];
            float wc = 1.0f - w.y;
            float ws = w.x;                 // conjugated twiddle
            float dr = a.x - bb.x, di2 = a.y - bb.y;
            int o = (pm << 1) + q;
            nxt[o]     = make_float2(a.x + bb.x, a.y + bb.y);
            nxt[o + m] = make_float2(wc * dr - ws * di2, wc * di2 + ws * dr);
        }
        __syncthreads();
        float2* tmp = cur; cur = nxt; nxt = tmp;
    }
    // cur == unnormalized time-domain packed output v[j] = y[2j] + i y[2j+1]

    const float scale = 1.0f / 2048.0f;
    float2* o2 = (float2*)out + (size_t)b * 1024;
    for (int j = t; j < 1024; j += 256) {
        float2 v = cur[1024 + j];
        o2[j] = make_float2(v.x * scale, v.y * scale);
    }
}

// ---------------------------------------------------------------------------
extern "C" void kernel_launch(void* const* d_in, const int* in_sizes, int n_in,
                              void* d_out, int out_size) {
    const float* x     = (const float*)d_in[0];
    const float* cond  = (const float*)d_in[1];
    const float* state = (const float*)d_in[2];
    const float* a_rg  = (const float*)d_in[3];
    const float* a_r1  = (const float*)d_in[4];
    const float* a_c1  = (const float*)d_in[5];
    const float* a_c2  = (const float*)d_in[6];
    const float* cw    = (const float*)d_in[7];
    const float* cb    = (const float*)d_in[8];
    float* out = (float*)d_out;

    int B = in_sizes[1];  // cond has B elements

    init_tw_kernel<<<9, 256>>>();
    init_params_kernel<<<(B + 255) / 256, 256>>>(cond, a_rg, a_r1, a_c1, a_c2,
                                                 cw, cb, B);
    preamp_fft_kernel<<<B, 256>>>(x, state, out);
}

// round 2
// speedup vs baseline: 1.4185x; 1.4185x over previous
#include <cuda_runtime.h>

// PreampGainLayer: DK-method preamp, FFT-domain circular filtering.
// Inputs (metadata order): x[B*2048], cond[B], state[B*4096],
//   alpha_rg[1], alpha_r1[1], alpha_c1[1], alpha_c2[1], cond_w[1], cond_b[1]
// Output: float[B*2048]

#define MM 2048   // complex FFT size (real length 4096)
#define PI_D 3.14159265358979323846

// twiddle table: {sin(pi*k/2048), 1 - cos(pi*k/2048)} computed in fp64
__device__ float2 g_tw[2049];
// per-batch filter params: DC, DS, DI, NC, NS, NI (6 used, stride 8)
__device__ float g_params[2048 * 8];

// ---------------------------------------------------------------------------
// merged init kernel: twiddles + per-batch DK params
// ---------------------------------------------------------------------------
__device__ void inv4(const double A[4][4], double O[4][4]) {
    double a[4][8];
    for (int r = 0; r < 4; r++) {
        for (int c = 0; c < 4; c++) a[r][c] = A[r][c];
        for (int c = 0; c < 4; c++) a[r][4 + c] = (r == c) ? 1.0 : 0.0;
    }
    for (int col = 0; col < 4; col++) {
        int piv = col;
        for (int r = col + 1; r < 4; r++)
            if (fabs(a[r][col]) > fabs(a[piv][col])) piv = r;
        if (piv != col)
            for (int c = 0; c < 8; c++) { double t = a[col][c]; a[col][c] = a[piv][c]; a[piv][c] = t; }
        double inv = 1.0 / a[col][col];
        for (int c = 0; c < 8; c++) a[col][c] *= inv;
        for (int r = 0; r < 4; r++) {
            if (r == col) continue;
            double f = a[r][col];
            for (int c = 0; c < 8; c++) a[r][c] -= f * a[col][c];
        }
    }
    for (int r = 0; r < 4; r++)
        for (int c = 0; c < 4; c++) O[r][c] = a[r][4 + c];
}

__global__ void init_kernel(const float* __restrict__ cond,
                            const float* __restrict__ a_rg,
                            const float* __restrict__ a_r1,
                            const float* __restrict__ a_c1,
                            const float* __restrict__ a_c2,
                            const float* __restrict__ cw,
                            const float* __restrict__ cb,
                            int B) {
    int gid = blockIdx.x * blockDim.x + threadIdx.x;

    if (gid <= 2048) {
        double th = PI_D * (double)gid / 2048.0;
        double s, c;
        sincos(th, &s, &c);
        g_tw[gid] = make_float2((float)s, (float)(1.0 - c));
    }

    int b = gid;
    if (b >= B) return;

    const double T = 1.0 / 44100.0;
    auto sig = [](double v) { return 1.0 / (1.0 + exp(-v)); };

    double RG = (0.9 + sig((double)a_rg[0]) * 0.2) * 1.0e6;
    double R1 = (0.99 + sig((double)a_r1[0]) * 0.02) * 4.7e5;
    double C1 = (0.9 + sig((double)a_c1[0]) * 0.2) * 3.3e-9;
    double C2 = (0.9 + sig((double)a_c2[0]) * 0.2) * 1.0e-9;

    double gr  = 1.0 / R1;
    double gx1 = 2.0 * C1 / T;
    double gx2 = 2.0 * C2 / T;

    double S[4][4] = {{gx1, -gx1, 0.0, 1.0},
                      {-gx1, gx1 + gr, 0.0, 0.0},
                      {0.0, 0.0, gx2, 0.0},
                      {1.0, 0.0, 0.0, 0.0}};
    double Si[4][4];
    inv4(S, Si);

    double PV[4][2], PX[4][2], PU[4];
    for (int i = 0; i < 4; i++) {
        PV[i][0] = Si[i][1] - Si[i][2];
        PV[i][1] = Si[i][2];
        PX[i][0] = Si[i][0] - Si[i][1];
        PX[i][1] = Si[i][2];
        PU[i]    = Si[i][3];
    }
    double Q[2][2], Ux[2][2];
    for (int c = 0; c < 2; c++) {
        Q[0][c]  = PV[1][c] - PV[2][c];
        Q[1][c]  = PV[2][c];
        Ux[0][c] = PV[0][c] - PV[1][c];
        Ux[1][c] = PV[2][c];
    }
    double UoV[2] = {PV[2][0], PV[2][1]};
    double Uu[2]  = {PV[3][0], PV[3][1]};
    double NXX[2][2];
    for (int c = 0; c < 2; c++) { NXX[0][c] = PX[0][c] - PX[1][c]; NXX[1][c] = PX[2][c]; }
    double zg1 = 2.0 * gx1, zg2 = 2.0 * gx2;
    double Ao[2][2] = {{zg1 * NXX[0][0] - 1.0, zg1 * NXX[0][1]},
                       {zg2 * NXX[1][0], zg2 * NXX[1][1] - 1.0}};
    double BXU0 = PU[0] - PU[1], BXU1 = PU[2];
    double Bo[2] = {zg1 * BXU0, zg2 * BXU1};
    double Do[2] = {PX[2][0], PX[2][1]};
    double Eo = PU[2];

    double pot = sig((double)cond[b] * (double)cw[0] + (double)cb[0]);
    double p = (pow(10.0, pot) - 1.0) / 9.0;
    p = fmin(fmax(p, 1e-4), 1.0 - 1e-4);
    double d0 = (1.0 - p) * RG, d1 = p * RG;

    double M00 = d0 + Q[0][0], M01 = Q[0][1], M10 = Q[1][0], M11 = d1 + Q[1][1];
    double idet = 1.0 / (M00 * M11 - M01 * M10);
    double K[2][2] = {{M11 * idet, -M01 * idet}, {-M10 * idet, M00 * idet}};

    double ZU[2][2] = {{zg1 * Ux[0][0], zg1 * Ux[0][1]},
                       {zg2 * Ux[1][0], zg2 * Ux[1][1]}};
    double t1[2][2];
    for (int r = 0; r < 2; r++)
        for (int c = 0; c < 2; c++)
            t1[r][c] = ZU[r][0] * K[0][c] + ZU[r][1] * K[1][c];

    double A2[2][2], Bm[2], Dm[2];
    for (int r = 0; r < 2; r++)
        for (int c = 0; c < 2; c++)
            A2[r][c] = Ao[r][c] - (t1[r][0] * Ux[c][0] + t1[r][1] * Ux[c][1]);
    for (int r = 0; r < 2; r++)
        Bm[r] = Bo[r] - (t1[r][0] * Uu[0] + t1[r][1] * Uu[1]);
    double UoK[2];
    for (int c = 0; c < 2; c++)
        UoK[c] = UoV[0] * K[0][c] + UoV[1] * K[1][c];
    for (int c = 0; c < 2; c++)
        Dm[c] = Do[c] - (UoK[0] * Ux[c][0] + UoK[1] * Ux[c][1]);
    double Em = Eo - (UoK[0] * Uu[0] + UoK[1] * Uu[1]);

    double tr  = A2[0][0] + A2[1][1];
    double det = A2[0][0] * A2[1][1] - A2[0][1] * A2[1][0];
    double m2[2][2];
    for (int r = 0; r < 2; r++)
        for (int c = 0; c < 2; c++)
            m2[r][c] = A2[r][c] - Bm[r] * Dm[c];
    double tr2  = m2[0][0] + m2[1][1];
    double det2 = m2[0][0] * m2[1][1] - m2[0][1] * m2[1][0];

    double n0 = Em;
    double n1 = -tr2 - (Em - 1.0) * tr;
    double n2 = det2 + (Em - 1.0) * det;

    float* P = &g_params[b * 8];
    P[0] = (float)(1.0 - tr + det);   // DC
    P[1] = (float)(1.0 + det);        // DS
    P[2] = (float)(det - 1.0);        // DI
    P[3] = (float)(n0 + n1 + n2);     // NC
    P[4] = (float)(n0 + n2);          // NS
    P[5] = (float)(n2 - n0);          // NI
}

// ---------------------------------------------------------------------------
// FFT filter kernel: one CTA per batch row; radix-4 Stockham, fused ends
// ---------------------------------------------------------------------------
__device__ __forceinline__ float2 heval(float sn, float omc,
                                        float DC, float DS, float DI,
                                        float NC, float NS, float NI) {
    float nr = NC - NS * omc;
    float ni = NI * sn;
    float dr = DC - DS * omc;
    float di = DI * sn;
    float inv = 1.0f / (dr * dr + di * di);
    return make_float2((nr * dr + ni * di) * inv, (ni * dr - nr * di) * inv);
}

// one radix-4 Stockham stage over 2048 points; sgn = -1 fwd, +1 inv
__device__ __forceinline__ void radix4_stage(const float2* __restrict__ cur,
                                             float2* __restrict__ nxt,
                                             int t, int m, float sgn) {
#pragma unroll
    for (int it = 0; it < 2; it++) {
        int i  = t + it * 256;
        int q  = i & (m - 1);
        int pm = i - q;
        float2 a0 = cur[i];
        float2 a1 = cur[i + 512];
        float2 a2 = cur[i + 1024];
        float2 a3 = cur[i + 1536];
        float2 w  = g_tw[pm << 1];         // angle = pi*pm/1024
        float c1 = 1.0f - w.y;
        float s1 = sgn * w.x;               // w1 = (c1, s1) = e^{i*sgn*theta}
        float c2 = c1 * c1 - s1 * s1;
        float s2 = 2.0f * c1 * s1;
        float c3 = c1 * c2 - s1 * s2;
        float s3 = s1 * c2 + c1 * s2;

        float p02x = a0.x + a2.x, p02y = a0.y + a2.y;
        float m02x = a0.x - a2.x, m02y = a0.y - a2.y;
        float p13x = a1.x + a3.x, p13y = a1.y + a3.y;
        float m13x = a1.x - a3.x, m13y = a1.y - a3.y;

        // b1raw = m02 + sgn*i*m13 ; b3raw = m02 - sgn*i*m13
        float b1rx = m02x - sgn * m13y, b1ry = m02y + sgn * m13x;
        float b3rx = m02x + sgn * m13y, b3ry = m02y - sgn * m13x;
        float b2rx = p02x - p13x,       b2ry = p02y - p13y;

        int o = (pm << 2) + q;
        nxt[o]         = make_float2(p02x + p13x, p02y + p13y);
        nxt[o + m]     = make_float2(c1 * b1rx - s1 * b1ry, c1 * b1ry + s1 * b1rx);
        nxt[o + 2 * m] = make_float2(c2 * b2rx - s2 * b2ry, c2 * b2ry + s2 * b2rx);
        nxt[o + 3 * m] = make_float2(c3 * b3rx - s3 * b3ry, c3 * b3ry + s3 * b3rx);
    }
}

__global__ __launch_bounds__(256) void preamp_fft_kernel(
    const float* __restrict__ x, const float* __restrict__ state,
    float* __restrict__ out) {
    __shared__ float2 sA[MM];
    __shared__ float2 sB[MM];

    const int b = blockIdx.x;
    const int t = threadIdx.x;

    // pack real input (state tail 2048 samples, then x 2048 samples) as complex
    const float4* st4 = (const float4*)(state + (size_t)b * 4096 + 2048);
    const float4* x4  = (const float4*)(x + (size_t)b * 2048);
    float4* sA4 = (float4*)sA;
#pragma unroll
    for (int k = t; k < 512; k += 256) sA4[k] = st4[k];
#pragma unroll
    for (int k = t; k < 512; k += 256) sA4[512 + k] = x4[k];

    const float* P = &g_params[b * 8];
    const float DC = P[0], DS = P[1], DI = P[2], NC = P[3], NS = P[4], NI = P[5];

    __syncthreads();

    float2* cur = sA;
    float2* nxt = sB;

    // ---- forward FFT: 5 radix-4 stages (== radix-2 m=1..512) ----
#pragma unroll
    for (int m = 1; m <= 256; m <<= 2) {
        radix4_stage(cur, nxt, t, m, -1.0f);
        __syncthreads();
        float2* tmp = cur; cur = nxt; nxt = tmp;
    }
    // remaining radix-2 stage (m=1024, unit twiddle) is fused into untangle:
    //   U[k]      = cur[k] + cur[k+1024]          (k in [0,1024))
    //   U[k+1024] = cur[k] - cur[k+1024]

    // ---- untangle -> rfft bins, multiply by h, repack -> V ----
#pragma unroll
    for (int it = 0; it < 4; it++) {
        int k = t + it * 256;
        if (k == 0) {
            float2 c0 = cur[0], cN = cur[1024];
            // bin 0 / bin 2048 from U[0]
            float U0x = c0.x + cN.x, U0y = c0.y + cN.y;
            float X0 = U0x + U0y;
            float XM = U0x - U0y;
            float h0 = NC / DC;
            float hM = (NC - 2.0f * NS) / (DC - 2.0f * DS);
            float Y0 = h0 * X0, YM = hM * XM;
            nxt[0] = make_float2(0.5f * (Y0 + YM), 0.5f * (Y0 - YM));
            // bin 1024 from U[1024]
            float Ux_ = c0.x - cN.x, Uy_ = c0.y - cN.y;
            float2 h = heval(1.0f, 1.0f, DC, DS, DI, NC, NS, NI);
            float yr = h.x * Ux_ + h.y * Uy_;
            float yi = h.y * Ux_ - h.x * Uy_;
            nxt[1024] = make_float2(yr, -yi);
        } else {
            float2 ck  = cur[k],        ck1 = cur[k + 1024];
            float2 cj  = cur[1024 - k], cj1 = cur[2048 - k];
            float2 Uk = make_float2(ck.x + ck1.x, ck.y + ck1.y);
            float2 Um = make_float2(cj.x - cj1.x, cj.y - cj1.y);
            float2 tw = g_tw[k];
            float sn = tw.x, omc = tw.y;
            float cs = 1.0f - omc;
            float uer = 0.5f * (Uk.x + Um.x), uei = 0.5f * (Uk.y - Um.y);
            float uor = 0.5f * (Uk.y + Um.y), uoi = -0.5f * (Uk.x - Um.x);
            float xr = uer + cs * uor + sn * uoi;
            float xi = uei + cs * uoi - sn * uor;
            float xmr = uer - (cs * uor + sn * uoi);
            float xmi = -uei - (sn * uor - cs * uoi);
            float2 hk = heval(sn, omc, DC, DS, DI, NC, NS, NI);
            float2 hm = heval(sn, 2.0f - omc, DC, DS, DI, NC, NS, NI);
            float ykr = hk.x * xr - hk.y * xi, yki = hk.x * xi + hk.y * xr;
            float ymr = hm.x * xmr - hm.y * xmi, ymi = hm.x * xmi + hm.y * xmr;
            float yer = 0.5f * (ykr + ymr), yei = 0.5f * (yki - ymi);
            float zr  = 0.5f * (ykr - ymr), zi  = 0.5f * (yki + ymi);
            float yor = cs * zr - sn * zi, yoi = cs * zi + sn * zr;
            nxt[k]        = make_float2(yer - yoi, yei + yor);
            nxt[2048 - k] = make_float2(yer + yoi, yor - yei);
        }
    }
    __syncthreads();
    { float2* tmp = cur; cur = nxt; nxt = tmp; }  // cur == V

    // ---- inverse FFT: 5 radix-4 stages (== radix-2 m=1..512) ----
#pragma unroll
    for (int m = 1; m <= 256; m <<= 2) {
        radix4_stage(cur, nxt, t, m, 1.0f);
        __syncthreads();
        float2* tmp = cur; cur = nxt; nxt = tmp;
    }
    // final inverse radix-2 stage (m=1024, unit twiddle) fused into the store:
    //   v[1024+j] = cur[j] - cur[j+1024]  -> y[2048..4095]

    const float scale = 1.0f / 2048.0f;
    float4* o4 = (float4*)(out + (size_t)b * 2048);
#pragma unroll
    for (int j = t; j < 512; j += 256) {
        float2 u0 = cur[2 * j],     l0 = cur[2 * j + 1024];
        float2 u1 = cur[2 * j + 1], l1 = cur[2 * j + 1025];
        o4[j] = make_float4((u0.x - l0.x) * scale, (u0.y - l0.y) * scale,
                            (u1.x - l1.x) * scale, (u1.y - l1.y) * scale);
    }
}

// ---------------------------------------------------------------------------
extern "C" void kernel_launch(void* const* d_in, const int* in_sizes, int n_in,
                              void* d_out, int out_size) {
    const float* x     = (const float*)d_in[0];
    const float* cond  = (const float*)d_in[1];
    const float* state = (const float*)d_in[2];
    const float* a_rg  = (const float*)d_in[3];
    const float* a_r1  = (const float*)d_in[4];
    const float* a_c1  = (const float*)d_in[5];
    const float* a_c2  = (const float*)d_in[6];
    const float* cw    = (const float*)d_in[7];
    const float* cb    = (const float*)d_in[8];
    float* out = (float*)d_out;

    int B = in_sizes[1];  // cond has B elements

    int blocks = (B + 255) / 256;
    if (blocks < 9) blocks = 9;   // must cover 2049 twiddle entries
    init_kernel<<<blocks, 256>>>(cond, a_rg, a_r1, a_c1, a_c2, cw, cb, B);
    preamp_fft_kernel<<<B, 256>>>(x, state, out);
}

// round 3
// speedup vs baseline: 2.2222x; 1.5666x over previous
#include <cuda_runtime.h>

// PreampGainLayer: DK-method preamp, FFT-domain circular filtering.
// Inputs (metadata order): x[B*2048], cond[B], state[B*4096],
//   alpha_rg[1], alpha_r1[1], alpha_c1[1], alpha_c2[1], cond_w[1], cond_b[1]
// Output: float[B*2048]

#define MM 2048   // complex FFT size (real length 4096)
#define PI_D 3.14159265358979323846

// twiddle table: {sin(pi*k/2048), 1 - cos(pi*k/2048)} computed in fp64
__device__ float2 g_tw[2049];
// per-batch filter params: DC, DS, DI, NC, NS, NI (6 used, stride 8)
__device__ float g_params[2048 * 8];

// bank swizzle: XOR bank bits [0,4) with bits [4,6) (duplicated): v ^ (((v>>4)&3)*5)
__device__ __forceinline__ int SW(int v) { return v ^ (((v >> 4) & 3) * 5); }

// ---------------------------------------------------------------------------
// init kernel: twiddles + per-batch DK params (analytic 4x4 inverse)
// ---------------------------------------------------------------------------
__global__ void init_kernel(const float* __restrict__ cond,
                            const float* __restrict__ a_rg,
                            const float* __restrict__ a_r1,
                            const float* __restrict__ a_c1,
                            const float* __restrict__ a_c2,
                            const float* __restrict__ cw,
                            const float* __restrict__ cb,
                            int B) {
    int gid = blockIdx.x * blockDim.x + threadIdx.x;

    if (gid <= 2048) {
        double th = PI_D * (double)gid / 2048.0;
        double s, c;
        sincos(th, &s, &c);
        g_tw[gid] = make_float2((float)s, (float)(1.0 - c));
    }

    int b = gid;
    if (b >= B) return;

    const double T = 1.0 / 44100.0;
    auto sig = [](double v) { return 1.0 / (1.0 + exp(-v)); };

    double RG = (0.9 + sig((double)a_rg[0]) * 0.2) * 1.0e6;
    double R1 = (0.99 + sig((double)a_r1[0]) * 0.02) * 4.7e5;
    double C1 = (0.9 + sig((double)a_c1[0]) * 0.2) * 3.3e-9;
    double C2 = (0.9 + sig((double)a_c2[0]) * 0.2) * 1.0e-9;

    double g   = 1.0 / R1;      // gr
    double a   = 2.0 * C1 / T;  // gx1
    double h   = 2.0 * C2 / T;  // gx2

    // Analytic inverse of S = [[a,-a,0,1],[-a,a+g,0,0],[0,0,h,0],[1,0,0,0]]
    double iag = 1.0 / (a + g);
    double ih  = 1.0 / h;
    double Si[4][4] = {
        {0.0, 0.0,     0.0, 1.0},
        {0.0, iag,     0.0, a * iag},
        {0.0, 0.0,     ih,  0.0},
        {1.0, a * iag, 0.0, -a * g * iag}};

    double PV[4][2], PX[4][2], PU[4];
    for (int i = 0; i < 4; i++) {
        PV[i][0] = Si[i][1] - Si[i][2];
        PV[i][1] = Si[i][2];
        PX[i][0] = Si[i][0] - Si[i][1];
        PX[i][1] = Si[i][2];
        PU[i]    = Si[i][3];
    }
    double Q[2][2], Ux[2][2];
    for (int c = 0; c < 2; c++) {
        Q[0][c]  = PV[1][c] - PV[2][c];
        Q[1][c]  = PV[2][c];
        Ux[0][c] = PV[0][c] - PV[1][c];
        Ux[1][c] = PV[2][c];
    }
    double UoV[2] = {PV[2][0], PV[2][1]};
    double Uu[2]  = {PV[3][0], PV[3][1]};
    double NXX[2][2];
    for (int c = 0; c < 2; c++) { NXX[0][c] = PX[0][c] - PX[1][c]; NXX[1][c] = PX[2][c]; }
    double zg1 = 2.0 * a, zg2 = 2.0 * h;
    double Ao[2][2] = {{zg1 * NXX[0][0] - 1.0, zg1 * NXX[0][1]},
                       {zg2 * NXX[1][0], zg2 * NXX[1][1] - 1.0}};
    double Bo[2] = {zg1 * (PU[0] - PU[1]), zg2 * PU[2]};
    double Do[2] = {PX[2][0], PX[2][1]};
    double Eo = PU[2];

    double pot = sig((double)cond[b] * (double)cw[0] + (double)cb[0]);
    double p = (exp(pot * 2.302585092994045684) - 1.0) / 9.0;  // 10^pot
    p = fmin(fmax(p, 1e-4), 1.0 - 1e-4);
    double d0 = (1.0 - p) * RG, d1 = p * RG;

    double M00 = d0 + Q[0][0], M01 = Q[0][1], M10 = Q[1][0], M11 = d1 + Q[1][1];
    double idet = 1.0 / (M00 * M11 - M01 * M10);
    double K[2][2] = {{M11 * idet, -M01 * idet}, {-M10 * idet, M00 * idet}};

    double ZU[2][2] = {{zg1 * Ux[0][0], zg1 * Ux[0][1]},
                       {zg2 * Ux[1][0], zg2 * Ux[1][1]}};
    double t1[2][2];
    for (int r = 0; r < 2; r++)
        for (int c = 0; c < 2; c++)
            t1[r][c] = ZU[r][0] * K[0][c] + ZU[r][1] * K[1][c];

    double A2[2][2], Bm[2], Dm[2];
    for (int r = 0; r < 2; r++)
        for (int c = 0; c < 2; c++)
            A2[r][c] = Ao[r][c] - (t1[r][0] * Ux[c][0] + t1[r][1] * Ux[c][1]);
    for (int r = 0; r < 2; r++)
        Bm[r] = Bo[r] - (t1[r][0] * Uu[0] + t1[r][1] * Uu[1]);
    double UoK[2];
    for (int c = 0; c < 2; c++)
        UoK[c] = UoV[0] * K[0][c] + UoV[1] * K[1][c];
    for (int c = 0; c < 2; c++)
        Dm[c] = Do[c] - (UoK[0] * Ux[c][0] + UoK[1] * Ux[c][1]);
    double Em = Eo - (UoK[0] * Uu[0] + UoK[1] * Uu[1]);

    double tr  = A2[0][0] + A2[1][1];
    double det = A2[0][0] * A2[1][1] - A2[0][1] * A2[1][0];
    double m2[2][2];
    for (int r = 0; r < 2; r++)
        for (int c = 0; c < 2; c++)
            m2[r][c] = A2[r][c] - Bm[r] * Dm[c];
    double tr2  = m2[0][0] + m2[1][1];
    double det2 = m2[0][0] * m2[1][1] - m2[0][1] * m2[1][0];

    double n0 = Em;
    double n1 = -tr2 - (Em - 1.0) * tr;
    double n2 = det2 + (Em - 1.0) * det;

    float* P = &g_params[b * 8];
    P[0] = (float)(1.0 - tr + det);   // DC
    P[1] = (float)(1.0 + det);        // DS
    P[2] = (float)(det - 1.0);        // DI
    P[3] = (float)(n0 + n1 + n2);     // NC
    P[4] = (float)(n0 + n2);          // NS
    P[5] = (float)(n2 - n0);          // NI
}

// ---------------------------------------------------------------------------
// FFT filter kernel: one CTA per batch row; radix-4 Stockham, swizzled smem
// ---------------------------------------------------------------------------
__device__ __forceinline__ float2 heval(float sn, float omc,
                                        float DC, float DS, float DI,
                                        float NC, float NS, float NI) {
    float nr = NC - NS * omc;
    float ni = NI * sn;
    float dr = DC - DS * omc;
    float di = DI * sn;
    float inv = 1.0f / (dr * dr + di * di);
    return make_float2((nr * dr + ni * di) * inv, (ni * dr - nr * di) * inv);
}

// radix-4 butterfly core; sgn = -1 fwd, +1 inv; twiddle w1=(c1,s1)
__device__ __forceinline__ void bfly4(float2 a0, float2 a1, float2 a2, float2 a3,
                                      float c1, float s1, float sgn,
                                      float2& o0, float2& o1, float2& o2, float2& o3) {
    float c2 = c1 * c1 - s1 * s1;
    float s2 = 2.0f * c1 * s1;
    float c3 = c1 * c2 - s1 * s2;
    float s3 = s1 * c2 + c1 * s2;

    float p02x = a0.x + a2.x, p02y = a0.y + a2.y;
    float m02x = a0.x - a2.x, m02y = a0.y - a2.y;
    float p13x = a1.x + a3.x, p13y = a1.y + a3.y;
    float m13x = a1.x - a3.x, m13y = a1.y - a3.y;

    float b1rx = m02x - sgn * m13y, b1ry = m02y + sgn * m13x;
    float b3rx = m02x + sgn * m13y, b3ry = m02y - sgn * m13x;
    float b2rx = p02x - p13x,       b2ry = p02y - p13y;

    o0 = make_float2(p02x + p13x, p02y + p13y);
    o1 = make_float2(c1 * b1rx - s1 * b1ry, c1 * b1ry + s1 * b1rx);
    o2 = make_float2(c2 * b2rx - s2 * b2ry, c2 * b2ry + s2 * b2rx);
    o3 = make_float2(c3 * b3rx - s3 * b3ry, c3 * b3ry + s3 * b3rx);
}

// one radix-4 Stockham stage over 2048 points through swizzled smem
__device__ __forceinline__ void radix4_stage(const float2* __restrict__ cur,
                                             float2* __restrict__ nxt,
                                             int t, int m, float sgn) {
#pragma unroll
    for (int it = 0; it < 2; it++) {
        int i  = t + it * 256;
        int q  = i & (m - 1);
        int pm = i - q;
        float2 a0 = cur[SW(i)];
        float2 a1 = cur[SW(i + 512)];
        float2 a2 = cur[SW(i + 1024)];
        float2 a3 = cur[SW(i + 1536)];
        float2 w  = g_tw[pm << 1];
        float c1 = 1.0f - w.y;
        float s1 = sgn * w.x;
        float2 o0, o1, o2, o3;
        bfly4(a0, a1, a2, a3, c1, s1, sgn, o0, o1, o2, o3);
        int o = (pm << 2) + q;
        nxt[SW(o)]         = o0;
        nxt[SW(o + m)]     = o1;
        nxt[SW(o + 2 * m)] = o2;
        nxt[SW(o + 3 * m)] = o3;
    }
}

__global__ __launch_bounds__(256) void preamp_fft_kernel(
    const float* __restrict__ x, const float* __restrict__ state,
    float* __restrict__ out) {
    __shared__ float2 sA[MM];
    __shared__ float2 sB[MM];

    const int b = blockIdx.x;
    const int t = threadIdx.x;

    // packed complex input: elem p = (real[2p], real[2p+1]);
    // real[0..2047] = state tail, real[2048..4095] = x
    const float2* st2 = (const float2*)(state + (size_t)b * 4096 + 2048);
    const float2* x2  = (const float2*)(x + (size_t)b * 2048);

    const float* P = &g_params[b * 8];
    const float DC = P[0], DS = P[1], DI = P[2], NC = P[3], NS = P[4], NI = P[5];

    // ---- load fused with forward radix-4 stage m=1 ----
#pragma unroll
    for (int it = 0; it < 2; it++) {
        int i = t + it * 256;                    // butterfly index, [0,512)
        float2 a0 = st2[i];                      // p = i        (<1024: state)
        float2 a1 = st2[i + 512];                // p = i+512    (<1024: state)
        float2 a2 = x2[i];                       // p = i+1024   (x region)
        float2 a3 = x2[i + 512];                 // p = i+1536   (x region)
        float2 w  = g_tw[i << 1];
        float c1 = 1.0f - w.y;
        float s1 = -w.x;
        float2 o0, o1, o2, o3;
        bfly4(a0, a1, a2, a3, c1, s1, -1.0f, o0, o1, o2, o3);
        int o = i << 2;
        sA[SW(o)]     = o0;
        sA[SW(o + 1)] = o1;
        sA[SW(o + 2)] = o2;
        sA[SW(o + 3)] = o3;
    }
    __syncthreads();

    float2* cur = sA;
    float2* nxt = sB;

    // ---- forward FFT: remaining radix-4 stages m=4,16,64,256 ----
#pragma unroll
    for (int m = 4; m <= 256; m <<= 2) {
        radix4_stage(cur, nxt, t, m, -1.0f);
        __syncthreads();
        float2* tmp = cur; cur = nxt; nxt = tmp;
    }
    // remaining radix-2 stage (m=1024, unit twiddle) fused into untangle:
    //   U[k]      = cur[k] + cur[k+1024]
    //   U[k+1024] = cur[k] - cur[k+1024]

    // ---- untangle -> rfft bins, multiply by h, repack -> V ----
#pragma unroll
    for (int it = 0; it < 4; it++) {
        int k = t + it * 256;
        if (k == 0) {
            float2 c0 = cur[SW(0)], cN = cur[SW(1024)];
            float U0x = c0.x + cN.x, U0y = c0.y + cN.y;
            float X0 = U0x + U0y;
            float XM = U0x - U0y;
            float h0 = NC / DC;
            float hM = (NC - 2.0f * NS) / (DC - 2.0f * DS);
            float Y0 = h0 * X0, YM = hM * XM;
            nxt[SW(0)] = make_float2(0.5f * (Y0 + YM), 0.5f * (Y0 - YM));
            float Ux_ = c0.x - cN.x, Uy_ = c0.y - cN.y;
            float2 h = heval(1.0f, 1.0f, DC, DS, DI, NC, NS, NI);
            float yr = h.x * Ux_ + h.y * Uy_;
            float yi = h.y * Ux_ - h.x * Uy_;
            nxt[SW(1024)] = make_float2(yr, -yi);
        } else {
            float2 ck  = cur[SW(k)],        ck1 = cur[SW(k + 1024)];
            float2 cj  = cur[SW(1024 - k)], cj1 = cur[SW(2048 - k)];
            float2 Uk = make_float2(ck.x + ck1.x, ck.y + ck1.y);
            float2 Um = make_float2(cj.x - cj1.x, cj.y - cj1.y);
            float2 tw = g_tw[k];
            float sn = tw.x, omc = tw.y;
            float cs = 1.0f - omc;
            float uer = 0.5f * (Uk.x + Um.x), uei = 0.5f * (Uk.y - Um.y);
            float uor = 0.5f * (Uk.y + Um.y), uoi = -0.5f * (Uk.x - Um.x);
            float xr = uer + cs * uor + sn * uoi;
            float xi = uei + cs * uoi - sn * uor;
            float xmr = uer - (cs * uor + sn * uoi);
            float xmi = -uei - (sn * uor - cs * uoi);
            float2 hk = heval(sn, omc, DC, DS, DI, NC, NS, NI);
            float2 hm = heval(sn, 2.0f - omc, DC, DS, DI, NC, NS, NI);
            float ykr = hk.x * xr - hk.y * xi, yki = hk.x * xi + hk.y * xr;
            float ymr = hm.x * xmr - hm.y * xmi, ymi = hm.x * xmi + hm.y * xmr;
            float yer = 0.5f * (ykr + ymr), yei = 0.5f * (yki - ymi);
            float zr  = 0.5f * (ykr - ymr), zi  = 0.5f * (yki + ymi);
            float yor = cs * zr - sn * zi, yoi = cs * zi + sn * zr;
            nxt[SW(k)]        = make_float2(yer - yoi, yei + yor);
            nxt[SW(2048 - k)] = make_float2(yer + yoi, yor - yei);
        }
    }
    __syncthreads();
    { float2* tmp = cur; cur = nxt; nxt = tmp; }  // cur == V

    // ---- inverse FFT: 5 radix-4 stages (m=1..256) ----
#pragma unroll
    for (int m = 1; m <= 256; m <<= 2) {
        radix4_stage(cur, nxt, t, m, 1.0f);
        __syncthreads();
        float2* tmp = cur; cur = nxt; nxt = tmp;
    }
    // final inverse radix-2 stage (m=1024, unit twiddle) fused into the store:
    //   v[1024+j] = cur[j] - cur[j+1024]  -> y[2048..4095]

    const float scale = 1.0f / 2048.0f;
    float4* o4 = (float4*)(out + (size_t)b * 2048);
#pragma unroll
    for (int j = t; j < 512; j += 256) {
        float2 u0 = cur[SW(2 * j)],     l0 = cur[SW(2 * j + 1024)];
        float2 u1 = cur[SW(2 * j + 1)], l1 = cur[SW(2 * j + 1025)];
        o4[j] = make_float4((u0.x - l0.x) * scale, (u0.y - l0.y) * scale,
                            (u1.x - l1.x) * scale, (u1.y - l1.y) * scale);
    }
}

// ---------------------------------------------------------------------------
extern "C" void kernel_launch(void* const* d_in, const int* in_sizes, int n_in,
                              void* d_out, int out_size) {
    const float* x     = (const float*)d_in[0];
    const float* cond  = (const float*)d_in[1];
    const float* state = (const float*)d_in[2];
    const float* a_rg  = (const float*)d_in[3];
    const float* a_r1  = (const float*)d_in[4];
    const float* a_c1  = (const float*)d_in[5];
    const float* a_c2  = (const float*)d_in[6];
    const float* cw    = (const float*)d_in[7];
    const float* cb    = (const float*)d_in[8];
    float* out = (float*)d_out;

    int B = in_sizes[1];  // cond has B elements

    int n = B > 2049 ? B : 2049;
    init_kernel<<<(n + 127) / 128, 128>>>(cond, a_rg, a_r1, a_c1, a_c2, cw, cb, B);
    preamp_fft_kernel<<<B, 256>>>(x, state, out);
}

// round 5
// speedup vs baseline: 2.6639x; 1.1988x over previous
#include <cuda_runtime.h>

// PreampGainLayer: DK-method preamp, FFT-domain circular filtering.
// Inputs (metadata order): x[B*2048], cond[B], state[B*4096],
//   alpha_rg[1], alpha_r1[1], alpha_c1[1], alpha_c2[1], cond_w[1], cond_b[1]
// Output: float[B*2048]

#define MM 2048
#define PI_D 3.14159265358979323846

// twiddle table: {sin(pi*k/2048), 1 - cos(pi*k/2048)}
__device__ float2 g_tw[2049];
// per-batch filter params: DC, DS, DI, NC, NS, NI (6 used, stride 8)
__device__ float g_params[2048 * 8];

// bank swizzle: bijective on low 4 bits per 16-aligned block; uses v bits 4..6
__device__ __forceinline__ int SW(int v) {
    return v ^ ((v >> 4) & 7) ^ ((v >> 3) & 8);
}

// ---------------------------------------------------------------------------
// init kernel: fp32 transcendentals, fp64 matrix chain (cancellation-safe)
// ---------------------------------------------------------------------------
__global__ void init_kernel(const float* __restrict__ cond,
                            const float* __restrict__ a_rg,
                            const float* __restrict__ a_r1,
                            const float* __restrict__ a_c1,
                            const float* __restrict__ a_c2,
                            const float* __restrict__ cw,
                            const float* __restrict__ cb,
                            int B) {
    int gid = blockIdx.x * blockDim.x + threadIdx.x;

    if (gid <= 2048) {
        float th = (float)gid * (float)(PI_D / 2048.0);
        float s  = sinf(th);
        float hs = sinf(0.5f * th);
        g_tw[gid] = make_float2(s, 2.0f * hs * hs);
    }

    int b = gid;
    if (b >= B) return;

    auto sigf = [](float v) { return 1.0f / (1.0f + expf(-v)); };

    const double T = 1.0 / 44100.0;
    double RG = (0.9 + (double)sigf(a_rg[0]) * 0.2) * 1.0e6;
    double R1 = (0.99 + (double)sigf(a_r1[0]) * 0.02) * 4.7e5;
    double C1 = (0.9 + (double)sigf(a_c1[0]) * 0.2) * 3.3e-9;
    double C2 = (0.9 + (double)sigf(a_c2[0]) * 0.2) * 1.0e-9;

    double g = 1.0 / R1;
    double a = 2.0 * C1 / T;
    double h = 2.0 * C2 / T;

    // analytic inverse of S = [[a,-a,0,1],[-a,a+g,0,0],[0,0,h,0],[1,0,0,0]]
    double iag = 1.0 / (a + g);
    double ih  = 1.0 / h;
    double Si[4][4] = {
        {0.0, 0.0,     0.0, 1.0},
        {0.0, iag,     0.0, a * iag},
        {0.0, 0.0,     ih,  0.0},
        {1.0, a * iag, 0.0, -a * g * iag}};

    double PV[4][2], PX[4][2], PU[4];
    for (int i = 0; i < 4; i++) {
        PV[i][0] = Si[i][1] - Si[i][2];
        PV[i][1] = Si[i][2];
        PX[i][0] = Si[i][0] - Si[i][1];
        PX[i][1] = Si[i][2];
        PU[i]    = Si[i][3];
    }
    double Q[2][2], Ux[2][2];
    for (int c = 0; c < 2; c++) {
        Q[0][c]  = PV[1][c] - PV[2][c];
        Q[1][c]  = PV[2][c];
        Ux[0][c] = PV[0][c] - PV[1][c];
        Ux[1][c] = PV[2][c];
    }
    double UoV[2] = {PV[2][0], PV[2][1]};
    double Uu[2]  = {PV[3][0], PV[3][1]};
    double NXX[2][2];
    for (int c = 0; c < 2; c++) { NXX[0][c] = PX[0][c] - PX[1][c]; NXX[1][c] = PX[2][c]; }
    double zg1 = 2.0 * a, zg2 = 2.0 * h;
    double Ao[2][2] = {{zg1 * NXX[0][0] - 1.0, zg1 * NXX[0][1]},
                       {zg2 * NXX[1][0], zg2 * NXX[1][1] - 1.0}};
    double Bo[2] = {zg1 * (PU[0] - PU[1]), zg2 * PU[2]};
    double Do[2] = {PX[2][0], PX[2][1]};
    double Eo = PU[2];

    float potf = sigf(cond[b] * cw[0] + cb[0]);
    float pf = (exp10f(potf) - 1.0f) * (1.0f / 9.0f);
    pf = fminf(fmaxf(pf, 1e-4f), 1.0f - 1e-4f);
    double p = (double)pf;
    double d0 = (1.0 - p) * RG, d1 = p * RG;

    double M00 = d0 + Q[0][0], M01 = Q[0][1], M10 = Q[1][0], M11 = d1 + Q[1][1];
    double idet = 1.0 / (M00 * M11 - M01 * M10);
    double K[2][2] = {{M11 * idet, -M01 * idet}, {-M10 * idet, M00 * idet}};

    double ZU[2][2] = {{zg1 * Ux[0][0], zg1 * Ux[0][1]},
                       {zg2 * Ux[1][0], zg2 * Ux[1][1]}};
    double t1[2][2];
    for (int r = 0; r < 2; r++)
        for (int c = 0; c < 2; c++)
            t1[r][c] = ZU[r][0] * K[0][c] + ZU[r][1] * K[1][c];

    double A2[2][2], Bm[2], Dm[2];
    for (int r = 0; r < 2; r++)
        for (int c = 0; c < 2; c++)
            A2[r][c] = Ao[r][c] - (t1[r][0] * Ux[c][0] + t1[r][1] * Ux[c][1]);
    for (int r = 0; r < 2; r++)
        Bm[r] = Bo[r] - (t1[r][0] * Uu[0] + t1[r][1] * Uu[1]);
    double UoK[2];
    for (int c = 0; c < 2; c++)
        UoK[c] = UoV[0] * K[0][c] + UoV[1] * K[1][c];
    for (int c = 0; c < 2; c++)
        Dm[c] = Do[c] - (UoK[0] * Ux[c][0] + UoK[1] * Ux[c][1]);
    double Em = Eo - (UoK[0] * Uu[0] + UoK[1] * Uu[1]);

    double tr  = A2[0][0] + A2[1][1];
    double det = A2[0][0] * A2[1][1] - A2[0][1] * A2[1][0];
    double m2[2][2];
    for (int r = 0; r < 2; r++)
        for (int c = 0; c < 2; c++)
            m2[r][c] = A2[r][c] - Bm[r] * Dm[c];
    double tr2  = m2[0][0] + m2[1][1];
    double det2 = m2[0][0] * m2[1][1] - m2[0][1] * m2[1][0];

    double n0 = Em;
    double n1 = -tr2 - (Em - 1.0) * tr;
    double n2 = det2 + (Em - 1.0) * det;

    float* P = &g_params[b * 8];
    P[0] = (float)(1.0 - tr + det);   // DC
    P[1] = (float)(1.0 + det);        // DS
    P[2] = (float)(det - 1.0);        // DI
    P[3] = (float)(n0 + n1 + n2);     // NC
    P[4] = (float)(n0 + n2);          // NS
    P[5] = (float)(n2 - n0);          // NI
}

// ---------------------------------------------------------------------------
// FFT filter kernel: radix-8 register Stockham, one CTA per batch row
// ---------------------------------------------------------------------------
__device__ __forceinline__ float2 heval(float sn, float omc,
                                        float DC, float DS, float DI,
                                        float NC, float NS, float NI) {
    float nr = NC - NS * omc;
    float ni = NI * sn;
    float dr = DC - DS * omc;
    float di = DI * sn;
    float inv = 1.0f / (dr * dr + di * di);
    return make_float2((nr * dr + ni * di) * inv, (ni * dr - nr * di) * inv);
}

// radix-4 butterfly core; sgn = -1 fwd, +1 inv; twiddle w1=(c1,s1)
// DIF/Stockham convention: twiddles applied to OUTPUTS.
__device__ __forceinline__ void bfly4(float2 a0, float2 a1, float2 a2, float2 a3,
                                      float c1, float s1, float sgn,
                                      float2& o0, float2& o1, float2& o2, float2& o3) {
    float c2 = c1 * c1 - s1 * s1;
    float s2 = 2.0f * c1 * s1;
    float c3 = c1 * c2 - s1 * s2;
    float s3 = s1 * c2 + c1 * s2;

    float p02x = a0.x + a2.x, p02y = a0.y + a2.y;
    float m02x = a0.x - a2.x, m02y = a0.y - a2.y;
    float p13x = a1.x + a3.x, p13y = a1.y + a3.y;
    float m13x = a1.x - a3.x, m13y = a1.y - a3.y;

    float b1rx = m02x - sgn * m13y, b1ry = m02y + sgn * m13x;
    float b3rx = m02x + sgn * m13y, b3ry = m02y - sgn * m13x;
    float b2rx = p02x - p13x,       b2ry = p02y - p13y;

    o0 = make_float2(p02x + p13x, p02y + p13y);
    o1 = make_float2(c1 * b1rx - s1 * b1ry, c1 * b1ry + s1 * b1rx);
    o2 = make_float2(c2 * b2rx - s2 * b2ry, c2 * b2ry + s2 * b2rx);
    o3 = make_float2(c3 * b3rx - s3 * b3ry, c3 * b3ry + s3 * b3rx);
}

// radix-8 core: composition of radix-4 stage at m (two butterflies: p and
// p+256/m, same q) with radix-2 stage at 4m (DIF: out_low = A+B,
// out_high = w2*(A-B)). Inputs a[j] = cur[i + 256*j], i = pm + q.
__device__ __forceinline__ void radix8_core(const float2 a[8], int q, int pm,
                                            float sgn, float2* __restrict__ nxt,
                                            int m) {
    const float r = 0.70710678118654752f;
    float2 w = g_tw[pm << 1];
    float c1 = 1.0f - w.y;
    float s1 = sgn * w.x;
    float c1b = r * (c1 - sgn * s1);   // w1 * e^{sgn*i*pi/4}
    float s1b = r * (sgn * c1 + s1);
    float2 w2 = g_tw[pm << 3];         // angle pi*4pm/1024
    float c2w = 1.0f - w2.y;
    float s2w = sgn * w2.x;

    float2 A0, A1, A2, A3, B0, B1, B2, B3;
    bfly4(a[0], a[2], a[4], a[6], c1, s1, sgn, A0, A1, A2, A3);
    bfly4(a[1], a[3], a[5], a[7], c1b, s1b, sgn, B0, B1, B2, B3);

    int o = (pm << 3) + q;
    float2 Aj[4] = {A0, A1, A2, A3};
    float2 Bj[4] = {B0, B1, B2, B3};
#pragma unroll
    for (int j = 0; j < 4; j++) {
        float sx = Aj[j].x + Bj[j].x, sy = Aj[j].y + Bj[j].y;
        float dx = Aj[j].x - Bj[j].x, dy = Aj[j].y - Bj[j].y;
        nxt[SW(o + j * m)]         = make_float2(sx, sy);
        nxt[SW(o + j * m + 4 * m)] = make_float2(c2w * dx - s2w * dy,
                                                 c2w * dy + s2w * dx);
    }
}

__device__ __forceinline__ void radix8_stage(const float2* __restrict__ cur,
                                             float2* __restrict__ nxt,
                                             int t, int m, float sgn) {
    int q  = t & (m - 1);
    int pm = t - q;
    float2 a[8];
#pragma unroll
    for (int j = 0; j < 8; j++) a[j] = cur[SW(t + 256 * j)];
    radix8_core(a, q, pm, sgn, nxt, m);
}

// untangle+filter for one conjugate pair: Uk=U[k], Um=U[2048-k]
__device__ __forceinline__ void untangle_pair(float2 Uk, float2 Um, float sn, float omc,
                                              float DC, float DS, float DI,
                                              float NC, float NS, float NI,
                                              float2& outk, float2& outm) {
    float cs = 1.0f - omc;
    float uer = 0.5f * (Uk.x + Um.x), uei = 0.5f * (Uk.y - Um.y);
    float uor = 0.5f * (Uk.y + Um.y), uoi = -0.5f * (Uk.x - Um.x);
    float xr = uer + cs * uor + sn * uoi;
    float xi = uei + cs * uoi - sn * uor;
    float xmr = uer - (cs * uor + sn * uoi);
    float xmi = -uei - (sn * uor - cs * uoi);
    float2 hk = heval(sn, omc, DC, DS, DI, NC, NS, NI);
    float2 hm = heval(sn, 2.0f - omc, DC, DS, DI, NC, NS, NI);
    float ykr = hk.x * xr - hk.y * xi, yki = hk.x * xi + hk.y * xr;
    float ymr = hm.x * xmr - hm.y * xmi, ymi = hm.x * xmi + hm.y * xmr;
    float yer = 0.5f * (ykr + ymr), yei = 0.5f * (yki - ymi);
    float zr  = 0.5f * (ykr - ymr), zi  = 0.5f * (yki + ymi);
    float yor = cs * zr - sn * zi, yoi = cs * zi + sn * zr;
    outk = make_float2(yer - yoi, yei + yor);
    outm = make_float2(yer + yoi, yor - yei);
}

__global__ __launch_bounds__(256) void preamp_fft_kernel(
    const float* __restrict__ x, const float* __restrict__ state,
    float* __restrict__ out) {
    __shared__ float2 sA[MM];
    __shared__ float2 sB[MM];

    const int b = blockIdx.x;
    const int t = threadIdx.x;

    const float2* st2 = (const float2*)(state + (size_t)b * 4096 + 2048);
    const float2* x2  = (const float2*)(x + (size_t)b * 2048);

    const float* P = &g_params[b * 8];
    const float DC = P[0], DS = P[1], DI = P[2], NC = P[3], NS = P[4], NI = P[5];

    // ---- forward radix-8 stage m=1 fused with gmem load ----
    {
        float2 a[8];
#pragma unroll
        for (int j = 0; j < 4; j++) a[j] = st2[t + 256 * j];
#pragma unroll
        for (int j = 0; j < 4; j++) a[4 + j] = x2[t + 256 * j];
        radix8_core(a, 0, t, -1.0f, sA, 1);
    }
    __syncthreads();

    // ---- forward radix-8 stages m=8, m=64 ----
    radix8_stage(sA, sB, t, 8, -1.0f);
    __syncthreads();
    radix8_stage(sB, sA, t, 64, -1.0f);
    __syncthreads();
    // remaining: unit-twiddle radix-4 (m=512) fused into untangle below.
    // U[q+512j] = 4-pt DFT outputs of sA[q+512j].

    // ---- untangle -> rfft bins, * h, repack -> V (into sB) ----
#pragma unroll
    for (int it = 0; it < 2; it++) {
        int q = t + it * 256;
        if (q == 0) {
            float2 g0 = sA[SW(0)], g1 = sA[SW(512)], g2 = sA[SW(1024)], g3 = sA[SW(1536)];
            float p02x = g0.x + g2.x, p02y = g0.y + g2.y;
            float m02x = g0.x - g2.x, m02y = g0.y - g2.y;
            float p13x = g1.x + g3.x, p13y = g1.y + g3.y;
            float m13x = g1.x - g3.x, m13y = g1.y - g3.y;
            float2 U0    = make_float2(p02x + p13x, p02y + p13y);
            float2 U512  = make_float2(m02x + m13y, m02y - m13x);
            float2 U1024 = make_float2(p02x - p13x, p02y - p13y);
            float2 U1536 = make_float2(m02x - m13y, m02y + m13x);
            // bins 0 / 2048
            float X0 = U0.x + U0.y;
            float XM = U0.x - U0.y;
            float h0 = NC / DC;
            float hM = (NC - 2.0f * NS) / (DC - 2.0f * DS);
            float Y0 = h0 * X0, YM = hM * XM;
            sB[SW(0)] = make_float2(0.5f * (Y0 + YM), 0.5f * (Y0 - YM));
            // bin 1024
            float2 h = heval(1.0f, 1.0f, DC, DS, DI, NC, NS, NI);
            float yr = h.x * U1024.x + h.y * U1024.y;
            float yi = h.y * U1024.x - h.x * U1024.y;
            sB[SW(1024)] = make_float2(yr, -yi);
            // pair k=512
            float2 tw = g_tw[512];
            float2 ok, om;
            untangle_pair(U512, U1536, tw.x, tw.y, DC, DS, DI, NC, NS, NI, ok, om);
            sB[SW(512)]  = ok;
            sB[SW(1536)] = om;
        } else {
            // butterfly q: need U[q] (j0), U[q+512] (j1)
            float2 g0 = sA[SW(q)], g1 = sA[SW(q + 512)],
                   g2 = sA[SW(q + 1024)], g3 = sA[SW(q + 1536)];
            float p02x = g0.x + g2.x, p02y = g0.y + g2.y;
            float m02x = g0.x - g2.x, m02y = g0.y - g2.y;
            float p13x = g1.x + g3.x, p13y = g1.y + g3.y;
            float m13x = g1.x - g3.x, m13y = g1.y - g3.y;
            float2 Uq0 = make_float2(p02x + p13x, p02y + p13y);      // U[q]
            float2 Uq1 = make_float2(m02x + m13y, m02y - m13x);      // U[q+512]
            // butterfly 512-q: need U[1536-q] (j2), U[2048-q] (j3)
            int q2 = 512 - q;
            float2 h0 = sA[SW(q2)], h1 = sA[SW(q2 + 512)],
                   h2 = sA[SW(q2 + 1024)], h3 = sA[SW(q2 + 1536)];
            float P02x = h0.x + h2.x, P02y = h0.y + h2.y;
            float M02x = h0.x - h2.x, M02y = h0.y - h2.y;
            float P13x = h1.x + h3.x, P13y = h1.y + h3.y;
            float M13x = h1.x - h3.x, M13y = h1.y - h3.y;
            float2 Ur2 = make_float2(P02x - P13x, P02y - P13y);      // U[1536-q]
            float2 Ur3 = make_float2(M02x - M13y, M02y + M13x);      // U[2048-q]

            float2 tw1 = g_tw[q];
            float2 ok, om;
            untangle_pair(Uq0, Ur3, tw1.x, tw1.y, DC, DS, DI, NC, NS, NI, ok, om);
            sB[SW(q)]        = ok;
            sB[SW(2048 - q)] = om;

            float2 tw2 = g_tw[512 + q];
            untangle_pair(Uq1, Ur2, tw2.x, tw2.y, DC, DS, DI, NC, NS, NI, ok, om);
            sB[SW(512 + q)]  = ok;
            sB[SW(1536 - q)] = om;
        }
    }
    __syncthreads();

    // ---- inverse radix-8 stages m=1, 8, 64 ----
    radix8_stage(sB, sA, t, 1, 1.0f);
    __syncthreads();
    radix8_stage(sA, sB, t, 8, 1.0f);
    __syncthreads();
    radix8_stage(sB, sA, t, 64, 1.0f);
    __syncthreads();
    // final unit-twiddle radix-4 (m=512) fused into store: need outputs j=2,3
    //   o2 = (g0+g2)-(g1+g3) -> sample 1024+q ; o3 = m02 + i*m13 -> sample 1536+q

    const float scale = 1.0f / 2048.0f;
    float4* o4 = (float4*)(out + (size_t)b * 2048);
    {
        float2 r2[2], r3[2];
#pragma unroll
        for (int u = 0; u < 2; u++) {
            int q = 2 * t + u;
            float2 g0 = sA[SW(q)], g1 = sA[SW(q + 512)],
                   g2 = sA[SW(q + 1024)], g3 = sA[SW(q + 1536)];
            float p02x = g0.x + g2.x, p02y = g0.y + g2.y;
            float m02x = g0.x - g2.x, m02y = g0.y - g2.y;
            float p13x = g1.x + g3.x, p13y = g1.y + g3.y;
            float m13x = g1.x - g3.x, m13y = g1.y - g3.y;
            r2[u] = make_float2((p02x - p13x) * scale, (p02y - p13y) * scale);
            r3[u] = make_float2((m02x + m13y) * scale, (m02y - m13x) * scale);
        }
        // samples (packed float2 idx): 1024+q -> out float2 idx q ; 1536+q -> 512+q
        o4[t]       = make_float4(r2[0].x, r2[0].y, r2[1].x, r2[1].y);
        o4[256 + t] = make_float4(r3[0].x, r3[0].y, r3[1].x, r3[1].y);
    }
}

// ---------------------------------------------------------------------------
extern "C" void kernel_launch(void* const* d_in, const int* in_sizes, int n_in,
                              void* d_out, int out_size) {
    const float* x     = (const float*)d_in[0];
    const float* cond  = (const float*)d_in[1];
    const float* state = (const float*)d_in[2];
    const float* a_rg  = (const float*)d_in[3];
    const float* a_r1  = (const float*)d_in[4];
    const float* a_c1  = (const float*)d_in[5];
    const float* a_c2  = (const float*)d_in[6];
    const float* cw    = (const float*)d_in[7];
    const float* cb    = (const float*)d_in[8];
    float* out = (float*)d_out;

    int B = in_sizes[1];  // cond has B elements

    int n = B > 2049 ? B : 2049;
    init_kernel<<<(n + 127) / 128, 128>>>(cond, a_rg, a_r1, a_c1, a_c2, cw, cb, B);
    preamp_fft_kernel<<<B, 256>>>(x, state, out);
}

// round 6
// speedup vs baseline: 2.7075x; 1.0164x over previous
#include <cuda_runtime.h>

// PreampGainLayer: DK-method preamp, FFT-domain circular filtering.
// Inputs (metadata order): x[B*2048], cond[B], state[B*4096],
//   alpha_rg[1], alpha_r1[1], alpha_c1[1], alpha_c2[1], cond_w[1], cond_b[1]
// Output: float[B*2048]

#define MM 2048
#define PI_D 3.14159265358979323846

// twiddle table: {sin(pi*k/2048), 1 - cos(pi*k/2048)}
__device__ float2 g_tw[2049];
// per-batch filter params: DC, DS, DI, NC, NS, NI (6 used, stride 8)
__device__ float g_params[2048 * 8];

// bank swizzle: bijective on low 4 bits per 16-aligned block; uses v bits 4..6
__device__ __forceinline__ int SW(int v) {
    return v ^ ((v >> 4) & 7) ^ ((v >> 3) & 8);
}

// ---------------------------------------------------------------------------
// init kernel: fp32 transcendentals, fp64 matrix chain (cancellation-safe)
// ---------------------------------------------------------------------------
__global__ void init_kernel(const float* __restrict__ cond,
                            const float* __restrict__ a_rg,
                            const float* __restrict__ a_r1,
                            const float* __restrict__ a_c1,
                            const float* __restrict__ a_c2,
                            const float* __restrict__ cw,
                            const float* __restrict__ cb,
                            int B) {
    int gid = blockIdx.x * blockDim.x + threadIdx.x;

    if (gid <= 2048) {
        float th = (float)gid * (float)(PI_D / 2048.0);
        float s  = sinf(th);
        float hs = sinf(0.5f * th);
        g_tw[gid] = make_float2(s, 2.0f * hs * hs);
    }

    int b = gid;
    if (b >= B) return;

    auto sigf = [](float v) { return 1.0f / (1.0f + expf(-v)); };

    const double T = 1.0 / 44100.0;
    double RG = (0.9 + (double)sigf(a_rg[0]) * 0.2) * 1.0e6;
    double R1 = (0.99 + (double)sigf(a_r1[0]) * 0.02) * 4.7e5;
    double C1 = (0.9 + (double)sigf(a_c1[0]) * 0.2) * 3.3e-9;
    double C2 = (0.9 + (double)sigf(a_c2[0]) * 0.2) * 1.0e-9;

    double g = 1.0 / R1;
    double a = 2.0 * C1 / T;
    double h = 2.0 * C2 / T;

    // analytic inverse of S = [[a,-a,0,1],[-a,a+g,0,0],[0,0,h,0],[1,0,0,0]]
    double iag = 1.0 / (a + g);
    double ih  = 1.0 / h;
    double Si[4][4] = {
        {0.0, 0.0,     0.0, 1.0},
        {0.0, iag,     0.0, a * iag},
        {0.0, 0.0,     ih,  0.0},
        {1.0, a * iag, 0.0, -a * g * iag}};

    double PV[4][2], PX[4][2], PU[4];
    for (int i = 0; i < 4; i++) {
        PV[i][0] = Si[i][1] - Si[i][2];
        PV[i][1] = Si[i][2];
        PX[i][0] = Si[i][0] - Si[i][1];
        PX[i][1] = Si[i][2];
        PU[i]    = Si[i][3];
    }
    double Q[2][2], Ux[2][2];
    for (int c = 0; c < 2; c++) {
        Q[0][c]  = PV[1][c] - PV[2][c];
        Q[1][c]  = PV[2][c];
        Ux[0][c] = PV[0][c] - PV[1][c];
        Ux[1][c] = PV[2][c];
    }
    double UoV[2] = {PV[2][0], PV[2][1]};
    double Uu[2]  = {PV[3][0], PV[3][1]};
    double NXX[2][2];
    for (int c = 0; c < 2; c++) { NXX[0][c] = PX[0][c] - PX[1][c]; NXX[1][c] = PX[2][c]; }
    double zg1 = 2.0 * a, zg2 = 2.0 * h;
    double Ao[2][2] = {{zg1 * NXX[0][0] - 1.0, zg1 * NXX[0][1]},
                       {zg2 * NXX[1][0], zg2 * NXX[1][1] - 1.0}};
    double Bo[2] = {zg1 * (PU[0] - PU[1]), zg2 * PU[2]};
    double Do[2] = {PX[2][0], PX[2][1]};
    double Eo = PU[2];

    float potf = sigf(cond[b] * cw[0] + cb[0]);
    float pf = (exp10f(potf) - 1.0f) * (1.0f / 9.0f);
    pf = fminf(fmaxf(pf, 1e-4f), 1.0f - 1e-4f);
    double p = (double)pf;
    double d0 = (1.0 - p) * RG, d1 = p * RG;

    double M00 = d0 + Q[0][0], M01 = Q[0][1], M10 = Q[1][0], M11 = d1 + Q[1][1];
    double idet = 1.0 / (M00 * M11 - M01 * M10);
    double K[2][2] = {{M11 * idet, -M01 * idet}, {-M10 * idet, M00 * idet}};

    double ZU[2][2] = {{zg1 * Ux[0][0], zg1 * Ux[0][1]},
                       {zg2 * Ux[1][0], zg2 * Ux[1][1]}};
    double t1[2][2];
    for (int r = 0; r < 2; r++)
        for (int c = 0; c < 2; c++)
            t1[r][c] = ZU[r][0] * K[0][c] + ZU[r][1] * K[1][c];

    double A2[2][2], Bm[2], Dm[2];
    for (int r = 0; r < 2; r++)
        for (int c = 0; c < 2; c++)
            A2[r][c] = Ao[r][c] - (t1[r][0] * Ux[c][0] + t1[r][1] * Ux[c][1]);
    for (int r = 0; r < 2; r++)
        Bm[r] = Bo[r] - (t1[r][0] * Uu[0] + t1[r][1] * Uu[1]);
    double UoK[2];
    for (int c = 0; c < 2; c++)
        UoK[c] = UoV[0] * K[0][c] + UoV[1] * K[1][c];
    for (int c = 0; c < 2; c++)
        Dm[c] = Do[c] - (UoK[0] * Ux[c][0] + UoK[1] * Ux[c][1]);
    double Em = Eo - (UoK[0] * Uu[0] + UoK[1] * Uu[1]);

    double tr  = A2[0][0] + A2[1][1];
    double det = A2[0][0] * A2[1][1] - A2[0][1] * A2[1][0];
    double m2[2][2];
    for (int r = 0; r < 2; r++)
        for (int c = 0; c < 2; c++)
            m2[r][c] = A2[r][c] - Bm[r] * Dm[c];
    double tr2  = m2[0][0] + m2[1][1];
    double det2 = m2[0][0] * m2[1][1] - m2[0][1] * m2[1][0];

    double n0 = Em;
    double n1 = -tr2 - (Em - 1.0) * tr;
    double n2 = det2 + (Em - 1.0) * det;

    float* P = &g_params[b * 8];
    P[0] = (float)(1.0 - tr + det);   // DC
    P[1] = (float)(1.0 + det);        // DS
    P[2] = (float)(det - 1.0);        // DI
    P[3] = (float)(n0 + n1 + n2);     // NC
    P[4] = (float)(n0 + n2);          // NS
    P[5] = (float)(n2 - n0);          // NI
}

// ---------------------------------------------------------------------------
// FFT filter kernel: radix-8 register Stockham, one CTA per batch row
// ---------------------------------------------------------------------------

// radix-4 butterfly, DIF/Stockham: twiddles (c1..c3) applied to OUTPUTS.
__device__ __forceinline__ void bfly4(float2 a0, float2 a1, float2 a2, float2 a3,
                                      float c1, float s1, float c2, float s2,
                                      float c3, float s3, float sgn,
                                      float2& o0, float2& o1, float2& o2, float2& o3) {
    float p02x = a0.x + a2.x, p02y = a0.y + a2.y;
    float m02x = a0.x - a2.x, m02y = a0.y - a2.y;
    float p13x = a1.x + a3.x, p13y = a1.y + a3.y;
    float m13x = a1.x - a3.x, m13y = a1.y - a3.y;

    float b1rx = m02x - sgn * m13y, b1ry = m02y + sgn * m13x;
    float b3rx = m02x + sgn * m13y, b3ry = m02y - sgn * m13x;
    float b2rx = p02x - p13x,       b2ry = p02y - p13y;

    o0 = make_float2(p02x + p13x, p02y + p13y);
    o1 = make_float2(c1 * b1rx - s1 * b1ry, c1 * b1ry + s1 * b1rx);
    o2 = make_float2(c2 * b2rx - s2 * b2ry, c2 * b2ry + s2 * b2rx);
    o3 = make_float2(c3 * b3rx - s3 * b3ry, c3 * b3ry + s3 * b3rx);
}

// radix-8 core: radix-4 at m (butterflies p, p+256/m; same q) composed with
// DIF radix-2 at 4m (out_low = A+B, out_high = w2*(A-B)).
// B-butterfly twiddle powers derived analytically from A's (w1b = w1*e^{sgn i pi/4}).
__device__ __forceinline__ void radix8_core(const float2 a[8], int q, int pm,
                                            float sgn, float2* __restrict__ nxt,
                                            int m) {
    const float r = 0.70710678118654752f;
    float2 w = g_tw[pm << 1];
    float c1 = 1.0f - w.y, s1 = sgn * w.x;
    float c2 = c1 * c1 - s1 * s1, s2 = 2.0f * c1 * s1;
    float c3 = c1 * c2 - s1 * s2, s3 = s1 * c2 + c1 * s2;
    // w1b = w1*e^{sgn i pi/4}; w2b = w2*(sgn i); w3b = w3*e^{sgn i 3pi/4}
    float c1b = r * (c1 - sgn * s1), s1b = r * (sgn * c1 + s1);
    float c2b = -sgn * s2,           s2b = sgn * c2;
    float c3b = r * (-c3 - sgn * s3), s3b = r * (sgn * c3 - s3);
    float2 w2 = g_tw[pm << 3];
    float c2w = 1.0f - w2.y, s2w = sgn * w2.x;

    float2 A[4], B[4];
    bfly4(a[0], a[2], a[4], a[6], c1, s1, c2, s2, c3, s3, sgn,
          A[0], A[1], A[2], A[3]);
    bfly4(a[1], a[3], a[5], a[7], c1b, s1b, c2b, s2b, c3b, s3b, sgn,
          B[0], B[1], B[2], B[3]);

    int o = (pm << 3) + q;
    if (m == 1) {
        // q=0, o=8t: SW(8t+k) = SW(8t)^k (k<8; XOR masks use only bits >=3)
        int ob = SW(o);
#pragma unroll
        for (int j = 0; j < 4; j++) {
            float sx = A[j].x + B[j].x, sy = A[j].y + B[j].y;
            float dx = A[j].x - B[j].x, dy = A[j].y - B[j].y;
            nxt[ob ^ j]       = make_float2(sx, sy);
            nxt[ob ^ (j + 4)] = make_float2(c2w * dx - s2w * dy,
                                            c2w * dy + s2w * dx);
        }
    } else {
#pragma unroll
        for (int j = 0; j < 4; j++) {
            float sx = A[j].x + B[j].x, sy = A[j].y + B[j].y;
            float dx = A[j].x - B[j].x, dy = A[j].y - B[j].y;
            nxt[SW(o + j * m)]         = make_float2(sx, sy);
            nxt[SW(o + j * m + 4 * m)] = make_float2(c2w * dx - s2w * dy,
                                                     c2w * dy + s2w * dx);
        }
    }
}

__device__ __forceinline__ void radix8_stage(const float2* __restrict__ cur,
                                             float2* __restrict__ nxt,
                                             int t, int m, float sgn) {
    int q  = t & (m - 1);
    int pm = t - q;
    // SW(t + 256j) = SW(t) + 256j (XOR masks use only bits 3..6)
    int swt = SW(t);
    float2 a[8];
#pragma unroll
    for (int j = 0; j < 8; j++) a[j] = cur[swt + 256 * j];
    radix8_core(a, q, pm, sgn, nxt, m);
}

// untangle+filter for one conjugate pair: Uk=U[k], Um=U[2048-k].
// Single reciprocal for both h evaluations.
__device__ __forceinline__ void untangle_pair(float2 Uk, float2 Um, float sn, float omc,
                                              float DC, float DS, float DI,
                                              float NC, float NS, float NI,
                                              float2& outk, float2& outm) {
    float cs = 1.0f - omc;
    float uer = 0.5f * (Uk.x + Um.x), uei = 0.5f * (Uk.y - Um.y);
    float uor = 0.5f * (Uk.y + Um.y), uoi = -0.5f * (Uk.x - Um.x);
    float xr = uer + cs * uor + sn * uoi;
    float xi = uei + cs * uoi - sn * uor;
    float xmr = uer - (cs * uor + sn * uoi);
    float xmi = -uei - (sn * uor - cs * uoi);

    float omc2 = 2.0f - omc;
    float d1r = DC - DS * omc,  d1i = DI * sn;
    float n1r = NC - NS * omc,  n1i = NI * sn;
    float d2r = DC - DS * omc2, n2r = NC - NS * omc2;
    float q1 = d1r * d1r + d1i * d1i;
    float q2 = d2r * d2r + d1i * d1i;
    float inv = 1.0f / (q1 * q2);
    float i1 = inv * q2, i2 = inv * q1;
    float hkx = (n1r * d1r + n1i * d1i) * i1, hky = (n1i * d1r - n1r * d1i) * i1;
    float hmx = (n2r * d2r + n1i * d1i) * i2, hmy = (n1i * d2r - n2r * d1i) * i2;

    float ykr = hkx * xr - hky * xi, yki = hkx * xi + hky * xr;
    float ymr = hmx * xmr - hmy * xmi, ymi = hmx * xmi + hmy * xmr;
    float yer = 0.5f * (ykr + ymr), yei = 0.5f * (yki - ymi);
    float zr  = 0.5f * (ykr - ymr), zi  = 0.5f * (yki + ymi);
    float yor = cs * zr - sn * zi, yoi = cs * zi + sn * zr;
    outk = make_float2(yer - yoi, yei + yor);
    outm = make_float2(yer + yoi, yor - yei);
}

__global__ __launch_bounds__(256, 4) void preamp_fft_kernel(
    const float* __restrict__ x, const float* __restrict__ state,
    float* __restrict__ out) {
    __shared__ float2 sA[MM];
    __shared__ float2 sB[MM];

    const int b = blockIdx.x;
    const int t = threadIdx.x;

    const float2* st2 = (const float2*)(state + (size_t)b * 4096 + 2048);
    const float2* x2  = (const float2*)(x + (size_t)b * 2048);

    const float* P = &g_params[b * 8];
    const float DC = P[0], DS = P[1], DI = P[2], NC = P[3], NS = P[4], NI = P[5];

    // ---- forward radix-8 stage m=1 fused with gmem load ----
    {
        float2 a[8];
#pragma unroll
        for (int j = 0; j < 4; j++) a[j] = st2[t + 256 * j];
#pragma unroll
        for (int j = 0; j < 4; j++) a[4 + j] = x2[t + 256 * j];
        radix8_core(a, 0, t, -1.0f, sA, 1);
    }
    __syncthreads();

    // ---- forward radix-8 stages m=8, m=64 ----
    radix8_stage(sA, sB, t, 8, -1.0f);
    __syncthreads();
    radix8_stage(sB, sA, t, 64, -1.0f);
    __syncthreads();
    // remaining unit-twiddle radix-4 (m=512) fused into untangle below.

    // ---- untangle -> rfft bins, * h, repack -> V (into sB) ----
#pragma unroll
    for (int it = 0; it < 2; it++) {
        int q = t + it * 256;
        if (q == 0) {
            float2 g0 = sA[SW(0)], g1 = sA[SW(512)], g2 = sA[SW(1024)], g3 = sA[SW(1536)];
            float p02x = g0.x + g2.x, p02y = g0.y + g2.y;
            float m02x = g0.x - g2.x, m02y = g0.y - g2.y;
            float p13x = g1.x + g3.x, p13y = g1.y + g3.y;
            float m13x = g1.x - g3.x, m13y = g1.y - g3.y;
            float2 U0    = make_float2(p02x + p13x, p02y + p13y);
            float2 U512  = make_float2(m02x + m13y, m02y - m13x);
            float2 U1024 = make_float2(p02x - p13x, p02y - p13y);
            float2 U1536 = make_float2(m02x - m13y, m02y + m13x);
            // bins 0 / 2048
            float X0 = U0.x + U0.y;
            float XM = U0.x - U0.y;
            float h0 = NC / DC;
            float hM = (NC - 2.0f * NS) / (DC - 2.0f * DS);
            float Y0 = h0 * X0, YM = hM * XM;
            sB[SW(0)] = make_float2(0.5f * (Y0 + YM), 0.5f * (Y0 - YM));
            // bin 1024: h at sn=1, omc=1
            {
                float dr = DC - DS, di = DI;
                float nr = NC - NS, ni = NI;
                float inv = 1.0f / (dr * dr + di * di);
                float hx = (nr * dr + ni * di) * inv;
                float hy = (ni * dr - nr * di) * inv;
                float yr = hx * U1024.x + hy * U1024.y;
                float yi = hy * U1024.x - hx * U1024.y;
                sB[SW(1024)] = make_float2(yr, -yi);
            }
            // pair k=512
            float2 tw = g_tw[512];
            float2 ok, om;
            untangle_pair(U512, U1536, tw.x, tw.y, DC, DS, DI, NC, NS, NI, ok, om);
            sB[SW(512)]  = ok;
            sB[SW(1536)] = om;
        } else {
            float2 g0 = sA[SW(q)], g1 = sA[SW(q + 512)],
                   g2 = sA[SW(q + 1024)], g3 = sA[SW(q + 1536)];
            float p02x = g0.x + g2.x, p02y = g0.y + g2.y;
            float m02x = g0.x - g2.x, m02y = g0.y - g2.y;
            float p13x = g1.x + g3.x, p13y = g1.y + g3.y;
            float m13x = g1.x - g3.x, m13y = g1.y - g3.y;
            float2 Uq0 = make_float2(p02x + p13x, p02y + p13y);      // U[q]
            float2 Uq1 = make_float2(m02x + m13y, m02y - m13x);      // U[q+512]
            int q2 = 512 - q;
            float2 h0 = sA[SW(q2)], h1 = sA[SW(q2 + 512)],
                   h2 = sA[SW(q2 + 1024)], h3 = sA[SW(q2 + 1536)];
            float P02x = h0.x + h2.x, P02y = h0.y + h2.y;
            float M02x = h0.x - h2.x, M02y = h0.y - h2.y;
            float P13x = h1.x + h3.x, P13y = h1.y + h3.y;
            float M13x = h1.x - h3.x, M13y = h1.y - h3.y;
            float2 Ur2 = make_float2(P02x - P13x, P02y - P13y);      // U[1536-q]
            float2 Ur3 = make_float2(M02x - M13y, M02y + M13x);      // U[2048-q]

            float2 tw1 = g_tw[q];
            float2 ok, om;
            untangle_pair(Uq0, Ur3, tw1.x, tw1.y, DC, DS, DI, NC, NS, NI, ok, om);
            sB[SW(q)]        = ok;
            sB[SW(2048 - q)] = om;

            float2 tw2 = g_tw[512 + q];
            untangle_pair(Uq1, Ur2, tw2.x, tw2.y, DC, DS, DI, NC, NS, NI, ok, om);
            sB[SW(512 + q)]  = ok;
            sB[SW(1536 - q)] = om;
        }
    }
    __syncthreads();

    // ---- inverse radix-8 stages m=1, 8, 64 ----
    radix8_stage(sB, sA, t, 1, 1.0f);
    __syncthreads();
    radix8_stage(sA, sB, t, 8, 1.0f);
    __syncthreads();
    radix8_stage(sB, sA, t, 64, 1.0f);
    __syncthreads();
    // final unit-twiddle radix-4 (m=512) fused into store: outputs j=2,3

    const float scale = 1.0f / 2048.0f;
    float4* o4 = (float4*)(out + (size_t)b * 2048);
    {
        float2 r2[2], r3[2];
#pragma unroll
        for (int u = 0; u < 2; u++) {
            int q = 2 * t + u;
            float2 g0 = sA[SW(q)], g1 = sA[SW(q + 512)],
                   g2 = sA[SW(q + 1024)], g3 = sA[SW(q + 1536)];
            float p02x = g0.x + g2.x, p02y = g0.y + g2.y;
            float m02x = g0.x - g2.x, m02y = g0.y - g2.y;
            float p13x = g1.x + g3.x, p13y = g1.y + g3.y;
            float m13x = g1.x - g3.x, m13y = g1.y - g3.y;
            r2[u] = make_float2((p02x - p13x) * scale, (p02y - p13y) * scale);
            r3[u] = make_float2((m02x + m13y) * scale, (m02y - m13x) * scale);
        }
        o4[t]       = make_float4(r2[0].x, r2[0].y, r2[1].x, r2[1].y);
        o4[256 + t] = make_float4(r3[0].x, r3[0].y, r3[1].x, r3[1].y);
    }
}

// ---------------------------------------------------------------------------
extern "C" void kernel_launch(void* const* d_in, const int* in_sizes, int n_in,
                              void* d_out, int out_size) {
    const float* x     = (const float*)d_in[0];
    const float* cond  = (const float*)d_in[1];
    const float* state = (const float*)d_in[2];
    const float* a_rg  = (const float*)d_in[3];
    const float* a_r1  = (const float*)d_in[4];
    const float* a_c1  = (const float*)d_in[5];
    const float* a_c2  = (const float*)d_in[6];
    const float* cw    = (const float*)d_in[7];
    const float* cb    = (const float*)d_in[8];
    float* out = (float*)d_out;

    int B = in_sizes[1];  // cond has B elements

    int n = B > 2049 ? B : 2049;
    init_kernel<<<(n + 127) / 128, 128>>>(cond, a_rg, a_r1, a_c1, a_c2, cw, cb, B);
    preamp_fft_kernel<<<B, 256>>>(x, state, out);
}